// round 1
// baseline (speedup 1.0000x reference)
#include <cuda_runtime.h>
#include <cstdint>

#define BUF_ROWS 65536
#define ROW_DIM  1024
#define NTHREADS 256

// Output layout (fp32, tuple flattened in reference-return order):
//   [0, 67108864)                buf (decayed buffer)
//   67108864                     buffer_occupancy
//   67108865                     average_age
//   [67108866, 67174402)         candidates (0.0 / 1.0)
//   67174402                     consolidation_pressure
//   [67174403, 134283267)        ltm_ready
#define OFF_BUF   ((size_t)0)
#define OFF_OCC   ((size_t)67108864)
#define OFF_AGE   ((size_t)67108865)
#define OFF_CAND  ((size_t)67108866)
#define OFF_PRESS ((size_t)67174402)
#define OFF_LTM   ((size_t)67174403)   // % 4 == 3  -> ltm stores must be scalar

// Accumulators: 256B-separated so each lands in a distinct L2 slice
// (addr->LTS hash uses bits {8,10-27}; 256B apart flips bit 8).
__device__ __align__(256) float g_age_sum[64];
__device__ __align__(256) int   g_occ[64];
__device__ __align__(256) int   g_press[64];
__device__ __align__(256) float g_istr[64];

// ---------------------------------------------------------------------------
// Kernel 0: input_strength = mean(|new_input|); reset accumulators.
// Re-zeros every launch so the graph replays deterministically.
// ---------------------------------------------------------------------------
__global__ void __launch_bounds__(NTHREADS) k_init(const float* __restrict__ new_input) {
    const int t = threadIdx.x;
    float4 v = reinterpret_cast<const float4*>(new_input)[t];  // 256*4 = 1024
    float p = fabsf(v.x) + fabsf(v.y) + fabsf(v.z) + fabsf(v.w);
    #pragma unroll
    for (int o = 16; o > 0; o >>= 1) p += __shfl_xor_sync(0xffffffffu, p, o);
    __shared__ float s[NTHREADS / 32];
    if ((t & 31) == 0) s[t >> 5] = p;
    __syncthreads();
    if (t == 0) {
        float tot = 0.0f;
        #pragma unroll
        for (int i = 0; i < NTHREADS / 32; i++) tot += s[i];
        g_istr[0]    = tot * (1.0f / (float)ROW_DIM);
        g_age_sum[0] = 0.0f;
        g_occ[0]     = 0;
        g_press[0]   = 0;
    }
}

// ---------------------------------------------------------------------------
// Kernel 1: one block per row. Read row once, write buf + ltm from registers.
// ---------------------------------------------------------------------------
__global__ void __launch_bounds__(NTHREADS) k_main(
    const float* __restrict__ new_input,
    const float* __restrict__ mem,
    const float* __restrict__ ages,
    const float* __restrict__ tags,
    const float* __restrict__ strs,
    const int*   __restrict__ wpos,
    const float* __restrict__ evp,
    const float* __restrict__ dtp,
    float*       __restrict__ out)
{
    const int r = blockIdx.x;
    const int t = threadIdx.x;

    int pos = wpos[0] % BUF_ROWS;
    if (pos < 0) pos += BUF_ROWS;
    const bool is_pos = (r == pos);

    const float ev  = evp[0];
    const float age = is_pos ? 0.0f : (ages[r] + dtp[0]);
    const float tag = is_pos ? ev   : tags[r];
    const float strength = is_pos ? (g_istr[0] * (1.0f + 0.5f * fabsf(ev)))
                                  : strs[r];

    float af = 1.0f - age * 1e-4f;
    af = fminf(fmaxf(af, 0.1f), 1.0f);
    const float decay = 0.95f * af * (1.0f + 0.3f * fabsf(tag));

    const float4* src = reinterpret_cast<const float4*>(
        is_pos ? new_input : (mem + (size_t)r * ROW_DIM));
    float4 v = src[t];
    v.x *= decay; v.y *= decay; v.z *= decay; v.w *= decay;

    // block-reduce row abs-sum
    float p = fabsf(v.x) + fabsf(v.y) + fabsf(v.z) + fabsf(v.w);
    #pragma unroll
    for (int o = 16; o > 0; o >>= 1) p += __shfl_xor_sync(0xffffffffu, p, o);
    __shared__ float s[NTHREADS / 32];
    __shared__ float s_sum;
    if ((t & 31) == 0) s[t >> 5] = p;
    __syncthreads();
    if (t == 0) {
        float tot = 0.0f;
        #pragma unroll
        for (int i = 0; i < NTHREADS / 32; i++) tot += s[i];
        s_sum = tot;
    }
    __syncthreads();
    const float row_sum = s_sum;

    const bool cand = (strength > 0.5f) && (age > 100.0f) && (row_sum > 0.1f);

    // buf: 16B-aligned region -> float4 stores
    reinterpret_cast<float4*>(out + OFF_BUF + (size_t)r * ROW_DIM)[t] = v;

    // ltm: base offset % 4 == 3 -> scalar stores only (misaligned for .128)
    float* ltm = out + OFF_LTM + (size_t)r * ROW_DIM + (size_t)t * 4;
    if (cand) {
        ltm[0] = v.x; ltm[1] = v.y; ltm[2] = v.z; ltm[3] = v.w;
    } else {
        ltm[0] = 0.0f; ltm[1] = 0.0f; ltm[2] = 0.0f; ltm[3] = 0.0f;
    }

    if (t == 0) {
        out[OFF_CAND + (size_t)r] = cand ? 1.0f : 0.0f;
        atomicAdd(&g_age_sum[0], age);
        if (row_sum > 0.01f) atomicAdd(&g_occ[0], 1);
        if (cand)            atomicAdd(&g_press[0], 1);
    }
}

// ---------------------------------------------------------------------------
// Kernel 2: finalize scalars (runs after k_main on the same stream).
// ---------------------------------------------------------------------------
__global__ void k_fin(float* __restrict__ out) {
    out[OFF_OCC]   = (float)g_occ[0] * (1.0f / (float)BUF_ROWS);
    out[OFF_AGE]   = g_age_sum[0]    * (1.0f / (float)BUF_ROWS);
    out[OFF_PRESS] = (float)g_press[0];
}

// ---------------------------------------------------------------------------
extern "C" void kernel_launch(void* const* d_in, const int* in_sizes, int n_in,
                              void* d_out, int out_size) {
    const float* new_input = (const float*)d_in[0];
    const float* mem       = (const float*)d_in[1];
    const float* ages      = (const float*)d_in[2];
    const float* tags      = (const float*)d_in[3];
    const float* strs      = (const float*)d_in[4];
    const int*   wpos      = (const int*)  d_in[5];
    const float* evp       = (const float*)d_in[6];
    const float* dtp       = (const float*)d_in[7];
    float*       out       = (float*)d_out;

    k_init<<<1, NTHREADS>>>(new_input);
    k_main<<<BUF_ROWS, NTHREADS>>>(new_input, mem, ages, tags, strs,
                                   wpos, evp, dtp, out);
    k_fin<<<1, 1>>>(out);
}

// round 2
// speedup vs baseline: 1.4011x; 1.4011x over previous
#include <cuda_runtime.h>
#include <cstdint>

#define BUF_ROWS 65536
#define ROW_DIM  1024
#define NT       256
#define NBLOCKS  1184   // 148 SMs * 8 resident blocks

// Output layout (fp32, flattened reference tuple):
//   [0, 67108864)          buf
//   67108864               buffer_occupancy
//   67108865               average_age
//   [67108866, 67174402)   candidates (0/1)
//   67174402               consolidation_pressure
//   [67174403, ...)        ltm_ready   (base % 4 == 3 -> base+1 is 16B-aligned)
#define OFF_OCC   ((size_t)67108864)
#define OFF_AGE   ((size_t)67108865)
#define OFF_CAND  ((size_t)67108866)
#define OFF_PRESS ((size_t)67174402)
#define OFF_LTM   ((size_t)67174403)

// Per-block partials, written unconditionally every run (no reset needed).
__device__ float g_age[NBLOCKS];
__device__ int   g_occ[NBLOCKS];
__device__ int   g_press[NBLOCKS];

// ---------------------------------------------------------------------------
// Persistent main kernel: grid-stride over rows, one row per block-iteration.
// Row read once; buf + ltm written from registers with fully aligned float4s.
// ---------------------------------------------------------------------------
__global__ void __launch_bounds__(NT) k_main(
    const float* __restrict__ new_input,
    const float* __restrict__ ages,
    const float* __restrict__ mem,
    const float* __restrict__ strs,
    const float* __restrict__ tags,
    const int*   __restrict__ wpos,
    const float* __restrict__ evp,
    const float* __restrict__ dtp,
    float*       __restrict__ out)
{
    const int t    = threadIdx.x;
    const int warp = t >> 5;
    const int lane = t & 31;

    int pos = wpos[0] % BUF_ROWS;
    if (pos < 0) pos += BUF_ROWS;
    const float ev = evp[0];
    const float dt = dtp[0];

    __shared__ float s_part[NT / 32];
    __shared__ float s_x[NT / 32];     // v.x of lane 0 of each warp
    __shared__ float s_sum;

    float age_acc = 0.0f;
    int   occ_acc = 0;
    int   press_acc = 0;

    for (int r = blockIdx.x; r < BUF_ROWS; r += NBLOCKS) {
        const bool  is_pos   = (r == pos);
        const float age      = is_pos ? 0.0f : (ages[r] + dt);
        const float tag      = is_pos ? ev   : tags[r];
        // pos row can never be a candidate (age=0 < 100), so strength value
        // there is irrelevant -> input_strength computation is dead code.
        const float strength = is_pos ? 0.0f : strs[r];

        float af = fminf(fmaxf(1.0f - age * 1e-4f, 0.1f), 1.0f);
        const float decay = 0.95f * af * (1.0f + 0.3f * fabsf(tag));

        const float4* src = reinterpret_cast<const float4*>(
            is_pos ? new_input : (mem + (size_t)r * ROW_DIM));
        float4 v = __ldcs(src + t);
        v.x *= decay; v.y *= decay; v.z *= decay; v.w *= decay;

        // buf store: 16B-aligned, full sectors, streaming
        __stcs(reinterpret_cast<float4*>(out + (size_t)r * ROW_DIM) + t, v);

        // block-reduce row abs-sum (post-decay values)
        float p = fabsf(v.x) + fabsf(v.y) + fabsf(v.z) + fabsf(v.w);
        #pragma unroll
        for (int o = 16; o > 0; o >>= 1) p += __shfl_xor_sync(0xffffffffu, p, o);
        if (lane == 0) { s_part[warp] = p; s_x[warp] = v.x; }
        __syncthreads();
        if (t == 0) {
            float tot = 0.0f;
            #pragma unroll
            for (int i = 0; i < NT / 32; i++) tot += s_part[i];
            s_sum = tot;
        }
        __syncthreads();
        const float row_sum = s_sum;

        // shifted-by-one value for the aligned ltm store
        float nx = __shfl_down_sync(0xffffffffu, v.x, 1);
        if (lane == 31 && warp < (NT / 32) - 1) nx = s_x[warp + 1];

        const bool cand = (strength > 0.5f) && (age > 100.0f) && (row_sum > 0.1f);
        if (!cand) { v.x = 0.0f; v.y = 0.0f; v.z = 0.0f; v.w = 0.0f; nx = 0.0f; }

        // ltm: base % 4 == 3; write [1, 1021) as aligned float4, edges scalar
        float* ltm = out + OFF_LTM + (size_t)r * ROW_DIM;
        if (t < NT - 1) {
            __stcs(reinterpret_cast<float4*>(ltm + 1) + t,
                   make_float4(v.y, v.z, v.w, nx));
        } else {
            ltm[ROW_DIM - 3] = v.y;
            ltm[ROW_DIM - 2] = v.z;
            ltm[ROW_DIM - 1] = v.w;
        }
        if (t == 0) {
            ltm[0] = v.x;
            out[OFF_CAND + (size_t)r] = cand ? 1.0f : 0.0f;
            age_acc   += age;
            occ_acc   += (row_sum > 0.01f) ? 1 : 0;
            press_acc += cand ? 1 : 0;
        }
        __syncthreads();   // protect s_part/s_x/s_sum reuse next iteration
    }

    if (t == 0) {
        g_age[blockIdx.x]   = age_acc;
        g_occ[blockIdx.x]   = occ_acc;
        g_press[blockIdx.x] = press_acc;
    }
}

// ---------------------------------------------------------------------------
// Finalize: reduce per-block partials, write the 3 scalar outputs.
// ---------------------------------------------------------------------------
__global__ void __launch_bounds__(NT) k_fin(float* __restrict__ out) {
    const int t = threadIdx.x;
    float a = 0.0f; int o = 0, c = 0;
    for (int i = t; i < NBLOCKS; i += NT) {
        a += g_age[i];
        o += g_occ[i];
        c += g_press[i];
    }
    #pragma unroll
    for (int s = 16; s > 0; s >>= 1) {
        a += __shfl_xor_sync(0xffffffffu, a, s);
        o += __shfl_xor_sync(0xffffffffu, o, s);
        c += __shfl_xor_sync(0xffffffffu, c, s);
    }
    __shared__ float sa[NT / 32];
    __shared__ int   so[NT / 32], sc[NT / 32];
    if ((t & 31) == 0) { sa[t >> 5] = a; so[t >> 5] = o; sc[t >> 5] = c; }
    __syncthreads();
    if (t == 0) {
        float ta = 0.0f; int to = 0, tc = 0;
        #pragma unroll
        for (int i = 0; i < NT / 32; i++) { ta += sa[i]; to += so[i]; tc += sc[i]; }
        out[OFF_OCC]   = (float)to * (1.0f / (float)BUF_ROWS);
        out[OFF_AGE]   = ta        * (1.0f / (float)BUF_ROWS);
        out[OFF_PRESS] = (float)tc;
    }
}

// ---------------------------------------------------------------------------
extern "C" void kernel_launch(void* const* d_in, const int* in_sizes, int n_in,
                              void* d_out, int out_size) {
    const float* new_input = (const float*)d_in[0];
    const float* mem       = (const float*)d_in[1];
    const float* ages      = (const float*)d_in[2];
    const float* tags      = (const float*)d_in[3];
    const float* strs      = (const float*)d_in[4];
    const int*   wpos      = (const int*)  d_in[5];
    const float* evp       = (const float*)d_in[6];
    const float* dtp       = (const float*)d_in[7];
    float*       out       = (float*)d_out;

    k_main<<<NBLOCKS, NT>>>(new_input, ages, mem, strs, tags, wpos, evp, dtp, out);
    k_fin<<<1, NT>>>(out);
}

// round 5
// speedup vs baseline: 1.5130x; 1.0798x over previous
#include <cuda_runtime.h>
#include <cstdint>

#define BUF_ROWS 65536
#define ROW_DIM  1024
#define NT       256
#define WPB      8                 // warps per block
#define NBLOCKS  444               // 148 SMs * 3 resident blocks
#define NWARPS   (NBLOCKS * WPB)   // 3552 row-warps

// Output layout (fp32, flattened reference tuple):
//   [0, 67108864)          buf
//   67108864               buffer_occupancy
//   67108865               average_age
//   [67108866, 67174402)   candidates (0/1)
//   67174402               consolidation_pressure
//   [67174403, ...)        ltm_ready  (base % 4 == 3 -> base+1 is 16B-aligned)
#define OFF_OCC   ((size_t)67108864)
#define OFF_AGE   ((size_t)67108865)
#define OFF_CAND  ((size_t)67108866)
#define OFF_PRESS ((size_t)67174402)
#define OFF_LTM   ((size_t)67174403)

__device__ float g_age[NBLOCKS];
__device__ int   g_occ[NBLOCKS];
__device__ int   g_press[NBLOCKS];
__device__ int   g_count = 0;      // last-block-done counter (reset by last block)

// ---------------------------------------------------------------------------
// Single persistent kernel. One WARP per row: the whole row lives in 8
// register float4s; no smem / no barriers in the hot loop; shift-by-one for
// the ltm alignment is pure warp shuffle. Finalization by the last block.
// ---------------------------------------------------------------------------
__global__ void __launch_bounds__(NT, 3) k_main(
    const float* __restrict__ new_input,
    const float* __restrict__ mem,
    const float* __restrict__ ages,
    const float* __restrict__ tags,
    const float* __restrict__ strs,
    const int*   __restrict__ wpos,
    const float* __restrict__ evp,
    const float* __restrict__ dtp,
    float*       __restrict__ out)
{
    const int t    = threadIdx.x;
    const int warp = t >> 5;
    const int lane = t & 31;
    const int gw   = blockIdx.x * WPB + warp;

    int pos = wpos[0] % BUF_ROWS;
    if (pos < 0) pos += BUF_ROWS;
    const float ev = evp[0];
    const float dt = dtp[0];

    float age_acc = 0.0f;
    int   occ_acc = 0, press_acc = 0;

    for (int r = gw; r < BUF_ROWS; r += NWARPS) {
        const bool  is_pos   = (r == pos);
        const float age      = is_pos ? 0.0f : (ages[r] + dt);
        const float tag      = is_pos ? ev   : tags[r];
        // pos row can never be a candidate (age=0 < 100): strength there is dead.
        const float strength = is_pos ? 0.0f : strs[r];

        float af = fminf(fmaxf(1.0f - age * 1e-4f, 0.1f), 1.0f);
        const float decay = 0.95f * af * (1.0f + 0.3f * fabsf(tag));

        const float4* src = reinterpret_cast<const float4*>(
            is_pos ? new_input : (mem + (size_t)r * ROW_DIM));

        // front-batched loads: 8 independent LDG.128 per thread
        float4 v[8];
        #pragma unroll
        for (int c = 0; c < 8; c++) v[c] = __ldcs(src + c * 32 + lane);

        float p = 0.0f;
        #pragma unroll
        for (int c = 0; c < 8; c++) {
            v[c].x *= decay; v[c].y *= decay; v[c].z *= decay; v[c].w *= decay;
            p += fabsf(v[c].x) + fabsf(v[c].y) + fabsf(v[c].z) + fabsf(v[c].w);
        }

        // buf store: aligned, streaming
        float4* bdst = reinterpret_cast<float4*>(out + (size_t)r * ROW_DIM);
        #pragma unroll
        for (int c = 0; c < 8; c++) __stcs(bdst + c * 32 + lane, v[c]);

        // warp-reduce row abs-sum (all lanes get it)
        #pragma unroll
        for (int o = 16; o > 0; o >>= 1) p += __shfl_xor_sync(0xffffffffu, p, o);

        const bool cand = (strength > 0.5f) && (age > 100.0f) && (p > 0.1f);

        // ltm: base % 4 == 3 -> aligned float4 stores at +1 with shift-by-one
        float* ltm = out + OFF_LTM + (size_t)r * ROW_DIM;
        const float4 zero = make_float4(0.f, 0.f, 0.f, 0.f);
        #pragma unroll
        for (int c = 0; c < 8; c++) {
            float xn      = (c < 7) ? v[c + 1].x : 0.0f;
            float nx_same = __shfl_down_sync(0xffffffffu, v[c].x, 1);
            float nx_next = __shfl_sync(0xffffffffu, xn, 0);
            float nx      = (lane == 31) ? nx_next : nx_same;
            float4 w = cand ? make_float4(v[c].y, v[c].z, v[c].w, nx) : zero;
            if (c < 7 || lane < 31)
                __stcs(reinterpret_cast<float4*>(ltm + 1) + c * 32 + lane, w);
        }
        if (lane == 31) {   // row tail: elements 1021..1023
            ltm[ROW_DIM - 3] = cand ? v[7].y : 0.0f;
            ltm[ROW_DIM - 2] = cand ? v[7].z : 0.0f;
            ltm[ROW_DIM - 1] = cand ? v[7].w : 0.0f;
        }
        if (lane == 0) {
            ltm[0] = cand ? v[0].x : 0.0f;
            out[OFF_CAND + (size_t)r] = cand ? 1.0f : 0.0f;
            age_acc   += age;
            occ_acc   += (p > 0.01f) ? 1 : 0;
            press_acc += cand ? 1 : 0;
        }
    }

    // ---- block-level reduction of per-warp accumulators ----
    __shared__ float sa[WPB];
    __shared__ int   so[WPB], sc[WPB];
    __shared__ int   s_last;
    if (lane == 0) { sa[warp] = age_acc; so[warp] = occ_acc; sc[warp] = press_acc; }
    __syncthreads();
    if (t == 0) {
        float a = 0.0f; int o = 0, c = 0;
        #pragma unroll
        for (int i = 0; i < WPB; i++) { a += sa[i]; o += so[i]; c += sc[i]; }
        g_age[blockIdx.x]   = a;
        g_occ[blockIdx.x]   = o;
        g_press[blockIdx.x] = c;
        __threadfence();
        s_last = (atomicAdd(&g_count, 1) == NBLOCKS - 1) ? 1 : 0;
    }
    __syncthreads();

    // ---- last block finalizes the 3 scalars and resets the counter ----
    if (s_last) {
        float a = 0.0f; int o = 0, c = 0;
        for (int i = t; i < NBLOCKS; i += NT) {
            a += __ldcg(&g_age[i]);
            o += __ldcg(&g_occ[i]);
            c += __ldcg(&g_press[i]);
        }
        #pragma unroll
        for (int s = 16; s > 0; s >>= 1) {
            a += __shfl_xor_sync(0xffffffffu, a, s);
            o += __shfl_xor_sync(0xffffffffu, o, s);
            c += __shfl_xor_sync(0xffffffffu, c, s);
        }
        __shared__ float fa[WPB];
        __shared__ int   fo[WPB], fc[WPB];
        if (lane == 0) { fa[warp] = a; fo[warp] = o; fc[warp] = c; }
        __syncthreads();
        if (t == 0) {
            float ta = 0.0f; int to = 0, tc = 0;
            #pragma unroll
            for (int i = 0; i < WPB; i++) { ta += fa[i]; to += fo[i]; tc += fc[i]; }
            out[OFF_OCC]   = (float)to * (1.0f / (float)BUF_ROWS);
            out[OFF_AGE]   = ta        * (1.0f / (float)BUF_ROWS);
            out[OFF_PRESS] = (float)tc;
            g_count = 0;   // reset for next graph replay
        }
    }
}

// ---------------------------------------------------------------------------
extern "C" void kernel_launch(void* const* d_in, const int* in_sizes, int n_in,
                              void* d_out, int out_size) {
    const float* new_input = (const float*)d_in[0];
    const float* mem       = (const float*)d_in[1];
    const float* ages      = (const float*)d_in[2];
    const float* tags      = (const float*)d_in[3];
    const float* strs      = (const float*)d_in[4];
    const int*   wpos      = (const int*)  d_in[5];
    const float* evp       = (const float*)d_in[6];
    const float* dtp       = (const float*)d_in[7];
    float*       out       = (float*)d_out;

    k_main<<<NBLOCKS, NT>>>(new_input, mem, ages, tags, strs, wpos, evp, dtp, out);
}

// round 8
// speedup vs baseline: 1.6349x; 1.0806x over previous
#include <cuda_runtime.h>
#include <cstdint>

#define BUF_ROWS 65536
#define ROW_DIM  1024
#define NT       256
#define WPB      8                 // warps per block
#define NBLOCKS  444               // 148 SMs * 3 resident blocks
#define GRAB     4                 // rows per steal (BUF_ROWS % GRAB == 0)

// Output layout (fp32, flattened reference tuple):
//   [0, 67108864)          buf
//   67108864               buffer_occupancy
//   67108865               average_age
//   [67108866, 67174402)   candidates (0/1)
//   67174402               consolidation_pressure
//   [67174403, ...)        ltm_ready  (base % 4 == 3 -> base+1 is 16B-aligned)
#define OFF_OCC   ((size_t)67108864)
#define OFF_AGE   ((size_t)67108865)
#define OFF_CAND  ((size_t)67108866)
#define OFF_PRESS ((size_t)67174402)
#define OFF_LTM   ((size_t)67174403)

__device__ float g_age[NBLOCKS];
__device__ int   g_occ[NBLOCKS];
__device__ int   g_press[NBLOCKS];
__device__ int   g_count = 0;   // blocks-done counter
__device__ int   g_next  = 0;   // work-steal row cursor (reset by last block)

// ---------------------------------------------------------------------------
// Single persistent kernel, warp-per-row, work-stealing dispatch.
// Row lives in 8 register float4s; no smem/barriers in the hot loop.
// ---------------------------------------------------------------------------
__global__ void __launch_bounds__(NT, 3) k_main(
    const float* __restrict__ new_input,
    const float* __restrict__ mem,
    const float* __restrict__ ages,
    const float* __restrict__ tags,
    const float* __restrict__ strs,
    const int*   __restrict__ wpos,
    const float* __restrict__ evp,
    const float* __restrict__ dtp,
    float*       __restrict__ out)
{
    const int t    = threadIdx.x;
    const int warp = t >> 5;
    const int lane = t & 31;

    int pos = wpos[0] % BUF_ROWS;
    if (pos < 0) pos += BUF_ROWS;
    const float ev = evp[0];
    const float dt = dtp[0];

    float age_acc = 0.0f;
    int   occ_acc = 0, press_acc = 0;

    for (;;) {
        int base = 0;
        if (lane == 0) base = atomicAdd(&g_next, GRAB);
        base = __shfl_sync(0xffffffffu, base, 0);
        if (base >= BUF_ROWS) break;

        // per-grab scalar vectors (base % 4 == 0 -> aligned float4)
        const float4 a4 = *reinterpret_cast<const float4*>(ages + base);
        const float4 t4 = *reinterpret_cast<const float4*>(tags + base);
        const float4 s4 = *reinterpret_cast<const float4*>(strs + base);

        #pragma unroll
        for (int j = 0; j < GRAB; j++) {
            const int   r      = base + j;
            const bool  is_pos = (r == pos);
            const float age_in = (j == 0) ? a4.x : (j == 1) ? a4.y : (j == 2) ? a4.z : a4.w;
            const float tag_in = (j == 0) ? t4.x : (j == 1) ? t4.y : (j == 2) ? t4.z : t4.w;
            const float str_in = (j == 0) ? s4.x : (j == 1) ? s4.y : (j == 2) ? s4.z : s4.w;

            const float age      = is_pos ? 0.0f : (age_in + dt);
            const float tag      = is_pos ? ev   : tag_in;
            // pos row can never be a candidate (age=0 < 100): strength is dead there.
            const float strength = is_pos ? 0.0f : str_in;

            float af = fminf(fmaxf(1.0f - age * 1e-4f, 0.1f), 1.0f);
            const float decay = 0.95f * af * (1.0f + 0.3f * fabsf(tag));

            const float4* src = reinterpret_cast<const float4*>(
                is_pos ? new_input : (mem + (size_t)r * ROW_DIM));

            // front-batched loads: 8 independent LDG.128 per thread
            float4 v[8];
            #pragma unroll
            for (int c = 0; c < 8; c++) v[c] = __ldcs(src + c * 32 + lane);

            float p = 0.0f;
            #pragma unroll
            for (int c = 0; c < 8; c++) {
                v[c].x *= decay; v[c].y *= decay; v[c].z *= decay; v[c].w *= decay;
                p += fabsf(v[c].x) + fabsf(v[c].y) + fabsf(v[c].z) + fabsf(v[c].w);
            }

            // buf store: aligned, streaming
            float4* bdst = reinterpret_cast<float4*>(out + (size_t)r * ROW_DIM);
            #pragma unroll
            for (int c = 0; c < 8; c++) __stcs(bdst + c * 32 + lane, v[c]);

            // warp-reduce row abs-sum
            #pragma unroll
            for (int o = 16; o > 0; o >>= 1) p += __shfl_xor_sync(0xffffffffu, p, o);

            const bool cand = (strength > 0.5f) && (age > 100.0f) && (p > 0.1f);

            // ltm: base % 4 == 3 -> aligned float4 stores at +1 with shift-by-one
            float* ltm = out + OFF_LTM + (size_t)r * ROW_DIM;
            const float4 zero = make_float4(0.f, 0.f, 0.f, 0.f);
            #pragma unroll
            for (int c = 0; c < 8; c++) {
                float xn      = (c < 7) ? v[c + 1].x : 0.0f;
                float nx_same = __shfl_down_sync(0xffffffffu, v[c].x, 1);
                float nx_next = __shfl_sync(0xffffffffu, xn, 0);
                float nx      = (lane == 31) ? nx_next : nx_same;
                float4 w = cand ? make_float4(v[c].y, v[c].z, v[c].w, nx) : zero;
                if (c < 7 || lane < 31)
                    __stcs(reinterpret_cast<float4*>(ltm + 1) + c * 32 + lane, w);
            }
            if (lane == 31) {   // row tail: elements 1021..1023
                ltm[ROW_DIM - 3] = cand ? v[7].y : 0.0f;
                ltm[ROW_DIM - 2] = cand ? v[7].z : 0.0f;
                ltm[ROW_DIM - 1] = cand ? v[7].w : 0.0f;
            }
            if (lane == 0) {
                ltm[0] = cand ? v[0].x : 0.0f;
                out[OFF_CAND + (size_t)r] = cand ? 1.0f : 0.0f;
                age_acc   += age;
                occ_acc   += (p > 0.01f) ? 1 : 0;
                press_acc += cand ? 1 : 0;
            }
        }
    }

    // ---- block-level reduction of per-warp accumulators ----
    __shared__ float sa[WPB];
    __shared__ int   so[WPB], sc[WPB];
    __shared__ int   s_last;
    if (lane == 0) { sa[warp] = age_acc; so[warp] = occ_acc; sc[warp] = press_acc; }
    __syncthreads();
    if (t == 0) {
        float a = 0.0f; int o = 0, c = 0;
        #pragma unroll
        for (int i = 0; i < WPB; i++) { a += sa[i]; o += so[i]; c += sc[i]; }
        g_age[blockIdx.x]   = a;
        g_occ[blockIdx.x]   = o;
        g_press[blockIdx.x] = c;
        __threadfence();
        s_last = (atomicAdd(&g_count, 1) == NBLOCKS - 1) ? 1 : 0;
    }
    __syncthreads();

    // ---- last block finalizes the 3 scalars and resets counters ----
    if (s_last) {
        float a = 0.0f; int o = 0, c = 0;
        for (int i = t; i < NBLOCKS; i += NT) {
            a += __ldcg(&g_age[i]);
            o += __ldcg(&g_occ[i]);
            c += __ldcg(&g_press[i]);
        }
        #pragma unroll
        for (int s = 16; s > 0; s >>= 1) {
            a += __shfl_xor_sync(0xffffffffu, a, s);
            o += __shfl_xor_sync(0xffffffffu, o, s);
            c += __shfl_xor_sync(0xffffffffu, c, s);
        }
        __shared__ float fa[WPB];
        __shared__ int   fo[WPB], fc[WPB];
        if (lane == 0) { fa[warp] = a; fo[warp] = o; fc[warp] = c; }
        __syncthreads();
        if (t == 0) {
            float ta = 0.0f; int to = 0, tc = 0;
            #pragma unroll
            for (int i = 0; i < WPB; i++) { ta += fa[i]; to += fo[i]; tc += fc[i]; }
            out[OFF_OCC]   = (float)to * (1.0f / (float)BUF_ROWS);
            out[OFF_AGE]   = ta        * (1.0f / (float)BUF_ROWS);
            out[OFF_PRESS] = (float)tc;
            g_count = 0;   // reset for next graph replay
            g_next  = 0;
        }
    }
}

// ---------------------------------------------------------------------------
extern "C" void kernel_launch(void* const* d_in, const int* in_sizes, int n_in,
                              void* d_out, int out_size) {
    const float* new_input = (const float*)d_in[0];
    const float* mem       = (const float*)d_in[1];
    const float* ages      = (const float*)d_in[2];
    const float* tags      = (const float*)d_in[3];
    const float* strs      = (const float*)d_in[4];
    const int*   wpos      = (const int*)  d_in[5];
    const float* evp       = (const float*)d_in[6];
    const float* dtp       = (const float*)d_in[7];
    float*       out       = (float*)d_out;

    k_main<<<NBLOCKS, NT>>>(new_input, mem, ages, tags, strs, wpos, evp, dtp, out);
}

// round 14
// speedup vs baseline: 1.6641x; 1.0179x over previous
#include <cuda_runtime.h>
#include <cstdint>

#define BUF_ROWS 65536
#define ROW_DIM  1024
#define NT       256
#define WPB      8                 // warps per block
#define NBLOCKS  444               // 148 SMs * 3 launched blocks
#define GRAB     4                 // rows per steal (BUF_ROWS % GRAB == 0)

// Output layout (fp32, flattened reference tuple):
//   [0, 67108864)          buf
//   67108864               buffer_occupancy
//   67108865               average_age
//   [67108866, 67174402)   candidates (0/1)   <-- base byte addr % 16 == 8 !
//   67174402               consolidation_pressure
//   [67174403, ...)        ltm_ready  (base % 4 == 3 -> base+1 is 16B-aligned)
#define OFF_OCC   ((size_t)67108864)
#define OFF_AGE   ((size_t)67108865)
#define OFF_CAND  ((size_t)67108866)
#define OFF_PRESS ((size_t)67174402)
#define OFF_LTM   ((size_t)67174403)

__device__ float g_age[NBLOCKS];
__device__ int   g_occ[NBLOCKS];
__device__ int   g_press[NBLOCKS];
__device__ int   g_count = 0;   // blocks-done counter
__device__ int   g_next  = 0;   // work-steal row cursor (reset by last block)

// ---------------------------------------------------------------------------
// Persistent kernel, warp-per-row, work-stealing, ROW-PIPELINED:
// next row's 8 LDG.128 are issued BEFORE the current row's 16 STG.128, so the
// read stream never drains while stores retire (double-buffered registers).
// ---------------------------------------------------------------------------
__global__ void __launch_bounds__(NT, 2) k_main(
    const float* __restrict__ new_input,
    const float* __restrict__ mem,
    const float* __restrict__ ages,
    const float* __restrict__ tags,
    const float* __restrict__ strs,
    const int*   __restrict__ wpos,
    const float* __restrict__ evp,
    const float* __restrict__ dtp,
    float*       __restrict__ out)
{
    const int t    = threadIdx.x;
    const int warp = t >> 5;
    const int lane = t & 31;

    int pos = wpos[0] % BUF_ROWS;
    if (pos < 0) pos += BUF_ROWS;
    const float ev = evp[0];
    const float dt = dtp[0];

    float age_acc = 0.0f;
    int   occ_acc = 0, press_acc = 0;

    // ---- steal first grab, prefetch its first row ----
    int base = 0;
    if (lane == 0) base = atomicAdd(&g_next, GRAB);
    base = __shfl_sync(0xffffffffu, base, 0);

    float4 v[2][8];   // double-buffered row registers
    if (base < BUF_ROWS) {
        const float4* s0 = reinterpret_cast<const float4*>(
            (base == pos) ? new_input : (mem + (size_t)base * ROW_DIM));
        #pragma unroll
        for (int c = 0; c < 8; c++) v[0][c] = __ldcs(s0 + c * 32 + lane);
    }

    while (base < BUF_ROWS) {
        // per-grab scalar vectors (base % 4 == 0 -> aligned float4)
        const float4 a4 = *reinterpret_cast<const float4*>(ages + base);
        const float4 t4 = *reinterpret_cast<const float4*>(tags + base);
        const float4 s4 = *reinterpret_cast<const float4*>(strs + base);

        float4 cand4;
        int nbase = BUF_ROWS;

        #pragma unroll
        for (int j = 0; j < GRAB; j++) {
            // ---- prefetch the NEXT row before storing the current one ----
            if (j < GRAB - 1) {
                const int rn = base + j + 1;
                const float4* sn = reinterpret_cast<const float4*>(
                    (rn == pos) ? new_input : (mem + (size_t)rn * ROW_DIM));
                #pragma unroll
                for (int c = 0; c < 8; c++)
                    v[(j + 1) & 1][c] = __ldcs(sn + c * 32 + lane);
            } else {
                if (lane == 0) nbase = atomicAdd(&g_next, GRAB);
                nbase = __shfl_sync(0xffffffffu, nbase, 0);
                if (nbase < BUF_ROWS) {
                    const float4* sn = reinterpret_cast<const float4*>(
                        (nbase == pos) ? new_input : (mem + (size_t)nbase * ROW_DIM));
                    #pragma unroll
                    for (int c = 0; c < 8; c++)
                        v[(j + 1) & 1][c] = __ldcs(sn + c * 32 + lane);
                }
            }

            // ---- process current row (buffer parity j&1) ----
            const int   r      = base + j;
            const bool  is_pos = (r == pos);
            const float age_in = (j == 0) ? a4.x : (j == 1) ? a4.y : (j == 2) ? a4.z : a4.w;
            const float tag_in = (j == 0) ? t4.x : (j == 1) ? t4.y : (j == 2) ? t4.z : t4.w;
            const float str_in = (j == 0) ? s4.x : (j == 1) ? s4.y : (j == 2) ? s4.z : s4.w;

            const float age      = is_pos ? 0.0f : (age_in + dt);
            const float tag      = is_pos ? ev   : tag_in;
            const float strength = is_pos ? 0.0f : str_in;   // pos row never a candidate

            float af = fminf(fmaxf(1.0f - age * 1e-4f, 0.1f), 1.0f);
            const float decay = 0.95f * af * (1.0f + 0.3f * fabsf(tag));

            float4* cur = v[j & 1];
            float p = 0.0f;
            #pragma unroll
            for (int c = 0; c < 8; c++) {
                cur[c].x *= decay; cur[c].y *= decay;
                cur[c].z *= decay; cur[c].w *= decay;
                p += fabsf(cur[c].x) + fabsf(cur[c].y)
                   + fabsf(cur[c].z) + fabsf(cur[c].w);
            }

            // buf store: aligned float4, streaming
            float4* bdst = reinterpret_cast<float4*>(out + (size_t)r * ROW_DIM);
            #pragma unroll
            for (int c = 0; c < 8; c++) __stcs(bdst + c * 32 + lane, cur[c]);

            // warp-reduce row abs-sum
            #pragma unroll
            for (int o = 16; o > 0; o >>= 1) p += __shfl_xor_sync(0xffffffffu, p, o);

            const bool cand = (strength > 0.5f) && (age > 100.0f) && (p > 0.1f);
            const float cf = cand ? 1.0f : 0.0f;
            if (j == 0) cand4.x = cf; else if (j == 1) cand4.y = cf;
            else if (j == 2) cand4.z = cf; else cand4.w = cf;

            // ltm: base % 4 == 3 -> aligned float4 stores at +1 with shift-by-one
            float* ltm = out + OFF_LTM + (size_t)r * ROW_DIM;
            const float4 zero = make_float4(0.f, 0.f, 0.f, 0.f);
            #pragma unroll
            for (int c = 0; c < 8; c++) {
                float xn      = (c < 7) ? cur[c + 1].x : 0.0f;
                float nx_same = __shfl_down_sync(0xffffffffu, cur[c].x, 1);
                float nx_next = __shfl_sync(0xffffffffu, xn, 0);
                float nx      = (lane == 31) ? nx_next : nx_same;
                float4 w = cand ? make_float4(cur[c].y, cur[c].z, cur[c].w, nx) : zero;
                if (c < 7 || lane < 31)
                    __stcs(reinterpret_cast<float4*>(ltm + 1) + c * 32 + lane, w);
            }
            if (lane == 31) {   // row tail: elements 1021..1023
                ltm[ROW_DIM - 3] = cand ? cur[7].y : 0.0f;
                ltm[ROW_DIM - 2] = cand ? cur[7].z : 0.0f;
                ltm[ROW_DIM - 1] = cand ? cur[7].w : 0.0f;
            }
            if (lane == 0) {
                ltm[0] = cand ? cur[0].x : 0.0f;
                age_acc   += age;
                occ_acc   += (p > 0.01f) ? 1 : 0;
                press_acc += cand ? 1 : 0;
            }
        }

        // batched candidate flags: OFF_CAND byte addr % 16 == 8, so the widest
        // legal vector here is float2 (8B-aligned). Two STG.64 per grab.
        if (lane == 0) {
            float* cdst = out + OFF_CAND + (size_t)base;
            __stcs(reinterpret_cast<float2*>(cdst),     make_float2(cand4.x, cand4.y));
            __stcs(reinterpret_cast<float2*>(cdst + 2), make_float2(cand4.z, cand4.w));
        }

        base = nbase;   // next grab's row 0 is already in flight in v[0]
    }

    // ---- block-level reduction of per-warp accumulators ----
    __shared__ float sa[WPB];
    __shared__ int   so[WPB], sc[WPB];
    __shared__ int   s_last;
    if (lane == 0) { sa[warp] = age_acc; so[warp] = occ_acc; sc[warp] = press_acc; }
    __syncthreads();
    if (t == 0) {
        float a = 0.0f; int o = 0, c = 0;
        #pragma unroll
        for (int i = 0; i < WPB; i++) { a += sa[i]; o += so[i]; c += sc[i]; }
        g_age[blockIdx.x]   = a;
        g_occ[blockIdx.x]   = o;
        g_press[blockIdx.x] = c;
        __threadfence();
        s_last = (atomicAdd(&g_count, 1) == NBLOCKS - 1) ? 1 : 0;
    }
    __syncthreads();

    // ---- last block finalizes the 3 scalars and resets counters ----
    if (s_last) {
        float a = 0.0f; int o = 0, c = 0;
        for (int i = t; i < NBLOCKS; i += NT) {
            a += __ldcg(&g_age[i]);
            o += __ldcg(&g_occ[i]);
            c += __ldcg(&g_press[i]);
        }
        #pragma unroll
        for (int s = 16; s > 0; s >>= 1) {
            a += __shfl_xor_sync(0xffffffffu, a, s);
            o += __shfl_xor_sync(0xffffffffu, o, s);
            c += __shfl_xor_sync(0xffffffffu, c, s);
        }
        __shared__ float fa[WPB];
        __shared__ int   fo[WPB], fc[WPB];
        if (lane == 0) { fa[warp] = a; fo[warp] = o; fc[warp] = c; }
        __syncthreads();
        if (t == 0) {
            float ta = 0.0f; int to = 0, tc = 0;
            #pragma unroll
            for (int i = 0; i < WPB; i++) { ta += fa[i]; to += fo[i]; tc += fc[i]; }
            out[OFF_OCC]   = (float)to * (1.0f / (float)BUF_ROWS);
            out[OFF_AGE]   = ta        * (1.0f / (float)BUF_ROWS);
            out[OFF_PRESS] = (float)tc;
            g_count = 0;   // reset for next graph replay
            g_next  = 0;
        }
    }
}

// ---------------------------------------------------------------------------
extern "C" void kernel_launch(void* const* d_in, const int* in_sizes, int n_in,
                              void* d_out, int out_size) {
    const float* new_input = (const float*)d_in[0];
    const float* mem       = (const float*)d_in[1];
    const float* ages      = (const float*)d_in[2];
    const float* tags      = (const float*)d_in[3];
    const float* strs      = (const float*)d_in[4];
    const int*   wpos      = (const int*)  d_in[5];
    const float* evp       = (const float*)d_in[6];
    const float* dtp       = (const float*)d_in[7];
    float*       out       = (float*)d_out;

    k_main<<<NBLOCKS, NT>>>(new_input, mem, ages, tags, strs, wpos, evp, dtp, out);
}